// round 1
// baseline (speedup 1.0000x reference)
#include <cuda_runtime.h>

#define S        4096
#define D_IN     128
#define H        4
#define D        32
#define HD       128
#define KSPLIT   4
#define KEYS_PER_SPLIT (S / KSPLIT)   // 1024
#define KT       64                    // key tile in smem
#define QB       256                   // queries per attention block (128 thr * 2)
#define NEGBIG   1e30f

// ---------------- scratch (device globals: no allocations allowed) ----------
__device__ float g_q[H * S * D];            // (h, s, d)
__device__ float g_k[H * S * D];
__device__ float g_v[H * S * D];
__device__ float g_bias[S];                 // key-validity additive bias (0 or -1e30)
__device__ float g_pm[H * S * KSPLIT];      // partial max
__device__ float g_pl[H * S * KSPLIT];      // partial sum-exp
__device__ float g_po[H * S * KSPLIT * D];  // partial (unnormalized) output

// ---------------- packed f32x2 math (2x FFMA throughput, PTX-only) ----------
__device__ __forceinline__ float2 ffma2(float2 a, float2 b, float2 c) {
    float2 r;
    asm("fma.rn.f32x2 %0, %1, %2, %3;"
        : "=l"(*reinterpret_cast<unsigned long long*>(&r))
        : "l"(*reinterpret_cast<unsigned long long*>(&a)),
          "l"(*reinterpret_cast<unsigned long long*>(&b)),
          "l"(*reinterpret_cast<unsigned long long*>(&c)));
    return r;
}
__device__ __forceinline__ float2 fmul2(float2 a, float2 b) {
    float2 r;
    asm("mul.rn.f32x2 %0, %1, %2;"
        : "=l"(*reinterpret_cast<unsigned long long*>(&r))
        : "l"(*reinterpret_cast<unsigned long long*>(&a)),
          "l"(*reinterpret_cast<unsigned long long*>(&b)));
    return r;
}

// ---------------- kernel 0: key-validity bias ------------------------------
__global__ void bias_kernel(const int* __restrict__ mask) {
    int t = blockIdx.x * blockDim.x + threadIdx.x;
    if (t < S) {
        int a = t >> 6, b = t & 63;
        g_bias[t] = (mask[a] && mask[b]) ? 0.0f : -NEGBIG;
    }
}

// ---------------- kernel 1: fused QKV projection (tiled GEMM) ---------------
// grid (S/32, 3): blockIdx.y selects Wq/Wk/Wv.  Block: 256 thr, 32 rows x 128 cols.
__global__ __launch_bounds__(256) void proj_kernel(
    const float* __restrict__ x,
    const float* __restrict__ Wq, const float* __restrict__ bq,
    const float* __restrict__ Wk, const float* __restrict__ bk,
    const float* __restrict__ Wv, const float* __restrict__ bv) {

    const int rowbase = blockIdx.x * 32;
    const int proj = blockIdx.y;
    const float* W    = (proj == 0) ? Wq : (proj == 1) ? Wk : Wv;
    const float* bias = (proj == 0) ? bq : (proj == 1) ? bk : bv;
    float* out        = (proj == 0) ? g_q : (proj == 1) ? g_k : g_v;

    __shared__ float sx[32 * D_IN];   // 16 KB
    __shared__ float sw[32 * HD];     // 16 KB (k-slab of W)

    const int tid = threadIdx.x;

    // load X tile (32 x 128), flat float4 copy
    {
        const float4* xg = (const float4*)(x + (size_t)rowbase * D_IN);
        float4* sx4 = (float4*)sx;
        #pragma unroll
        for (int i = 0; i < 4; i++) sx4[tid + i * 256] = xg[tid + i * 256];
    }

    const int ty = tid >> 4;   // 0..15 -> rows ty*2, ty*2+1
    const int tx = tid & 15;   // cols tx*8 .. tx*8+7

    float acc[2][8];
    #pragma unroll
    for (int r = 0; r < 2; r++)
        #pragma unroll
        for (int c = 0; c < 8; c++) acc[r][c] = 0.0f;

    for (int kk = 0; kk < 4; kk++) {
        __syncthreads();
        {
            const float4* wg = (const float4*)(W + (size_t)(kk * 32) * HD);
            float4* sw4 = (float4*)sw;
            #pragma unroll
            for (int i = 0; i < 4; i++) sw4[tid + i * 256] = wg[tid + i * 256];
        }
        __syncthreads();
        #pragma unroll
        for (int k = 0; k < 32; k++) {
            float x0 = sx[(ty * 2 + 0) * D_IN + kk * 32 + k];
            float x1 = sx[(ty * 2 + 1) * D_IN + kk * 32 + k];
            float4 w0 = *(const float4*)&sw[k * HD + tx * 8];
            float4 w1 = *(const float4*)&sw[k * HD + tx * 8 + 4];
            float wv[8] = {w0.x, w0.y, w0.z, w0.w, w1.x, w1.y, w1.z, w1.w};
            #pragma unroll
            for (int c = 0; c < 8; c++) {
                acc[0][c] = fmaf(x0, wv[c], acc[0][c]);
                acc[1][c] = fmaf(x1, wv[c], acc[1][c]);
            }
        }
    }

    #pragma unroll
    for (int r = 0; r < 2; r++) {
        int row = rowbase + ty * 2 + r;
        #pragma unroll
        for (int c = 0; c < 8; c++) {
            int col = tx * 8 + c;
            float v = acc[r][c] + bias[col];
            int h = col >> 5, d = col & 31;
            out[((size_t)h * S + row) * D + d] = v;
        }
    }
}

// ---------------- kernel 2: flash attention, split-K partials ---------------
// grid (S/QB=16, H=4, KSPLIT=4) = 256 blocks; 128 threads; 2 queries/thread.
__global__ __launch_bounds__(128) void attn_kernel() {
    const int qtile = blockIdx.x;
    const int h     = blockIdx.y;
    const int kc    = blockIdx.z;
    const int tid   = threadIdx.x;

    const int q0i = qtile * QB + tid;
    const int q1i = q0i + 128;

    __shared__ float sk[KT * D];      // 8 KB
    __shared__ float sv[KT * D];      // 8 KB
    __shared__ float sbias[KT];

    const float scale = 0.17677669529663687f;  // 1/sqrt(32)

    float2 q0p[16], q1p[16], o0p[16], o1p[16];
    {
        const float4* qg0 = (const float4*)(g_q + ((size_t)h * S + q0i) * D);
        const float4* qg1 = (const float4*)(g_q + ((size_t)h * S + q1i) * D);
        #pragma unroll
        for (int i = 0; i < 8; i++) {
            float4 a = qg0[i];
            q0p[2 * i]     = make_float2(a.x * scale, a.y * scale);
            q0p[2 * i + 1] = make_float2(a.z * scale, a.w * scale);
            float4 b = qg1[i];
            q1p[2 * i]     = make_float2(b.x * scale, b.y * scale);
            q1p[2 * i + 1] = make_float2(b.z * scale, b.w * scale);
            o0p[2 * i] = o0p[2 * i + 1] = make_float2(0.0f, 0.0f);
            o1p[2 * i] = o1p[2 * i + 1] = make_float2(0.0f, 0.0f);
        }
    }
    float m0 = -NEGBIG, m1 = -NEGBIG, l0 = 0.0f, l1 = 0.0f;

    const int kbase = kc * KEYS_PER_SPLIT;

    for (int jt = 0; jt < KEYS_PER_SPLIT / KT; jt++) {   // 16 tiles
        __syncthreads();
        {
            const float4* kg = (const float4*)(g_k + ((size_t)h * S + kbase + jt * KT) * D);
            const float4* vg = (const float4*)(g_v + ((size_t)h * S + kbase + jt * KT) * D);
            float4* sk4 = (float4*)sk;
            float4* sv4 = (float4*)sv;
            #pragma unroll
            for (int i = 0; i < 4; i++) {
                sk4[tid + i * 128] = kg[tid + i * 128];
                sv4[tid + i * 128] = vg[tid + i * 128];
            }
            if (tid < KT) sbias[tid] = g_bias[kbase + jt * KT + tid];
        }
        __syncthreads();

        for (int t = 0; t < KT; t++) {
            // --- scores: q . k for both queries (packed f32x2) ---
            const float4* kp = (const float4*)(sk + t * D);
            float2 a0 = make_float2(0.f, 0.f), b0 = make_float2(0.f, 0.f);
            float2 a1 = make_float2(0.f, 0.f), b1 = make_float2(0.f, 0.f);
            #pragma unroll
            for (int i = 0; i < 8; i++) {
                float4 kk = kp[i];
                float2 klo = make_float2(kk.x, kk.y);
                float2 khi = make_float2(kk.z, kk.w);
                a0 = ffma2(q0p[2 * i],     klo, a0);
                b0 = ffma2(q0p[2 * i + 1], khi, b0);
                a1 = ffma2(q1p[2 * i],     klo, a1);
                b1 = ffma2(q1p[2 * i + 1], khi, b1);
            }
            float bias_t = sbias[t];
            float s0 = (a0.x + b0.x) + (a0.y + b0.y) + bias_t;
            float s1 = (a1.x + b1.x) + (a1.y + b1.y) + bias_t;

            // --- online softmax (rescale only on new max; rare) ---
            if (s0 > m0) {
                float c = __expf(m0 - s0);
                l0 *= c;
                float2 c2 = make_float2(c, c);
                #pragma unroll
                for (int i = 0; i < 16; i++) o0p[i] = fmul2(o0p[i], c2);
                m0 = s0;
            }
            float p0 = __expf(s0 - m0);
            l0 += p0;
            if (s1 > m1) {
                float c = __expf(m1 - s1);
                l1 *= c;
                float2 c2 = make_float2(c, c);
                #pragma unroll
                for (int i = 0; i < 16; i++) o1p[i] = fmul2(o1p[i], c2);
                m1 = s1;
            }
            float p1 = __expf(s1 - m1);
            l1 += p1;

            // --- o += p * v (packed f32x2, v shared across both queries) ---
            const float4* vp = (const float4*)(sv + t * D);
            float2 p02 = make_float2(p0, p0), p12 = make_float2(p1, p1);
            #pragma unroll
            for (int i = 0; i < 8; i++) {
                float4 vv = vp[i];
                float2 vlo = make_float2(vv.x, vv.y);
                float2 vhi = make_float2(vv.z, vv.w);
                o0p[2 * i]     = ffma2(p02, vlo, o0p[2 * i]);
                o0p[2 * i + 1] = ffma2(p02, vhi, o0p[2 * i + 1]);
                o1p[2 * i]     = ffma2(p12, vlo, o1p[2 * i]);
                o1p[2 * i + 1] = ffma2(p12, vhi, o1p[2 * i + 1]);
            }
        }
    }

    // --- write partials ---
    int prow0 = ((h * S) + q0i) * KSPLIT + kc;
    int prow1 = ((h * S) + q1i) * KSPLIT + kc;
    g_pm[prow0] = m0; g_pl[prow0] = l0;
    g_pm[prow1] = m1; g_pl[prow1] = l1;
    float4* po0 = (float4*)(g_po + (size_t)prow0 * D);
    float4* po1 = (float4*)(g_po + (size_t)prow1 * D);
    #pragma unroll
    for (int i = 0; i < 8; i++) {
        po0[i] = make_float4(o0p[2 * i].x, o0p[2 * i].y, o0p[2 * i + 1].x, o0p[2 * i + 1].y);
        po1[i] = make_float4(o1p[2 * i].x, o1p[2 * i].y, o1p[2 * i + 1].x, o1p[2 * i + 1].y);
    }
}

// ---------------- kernel 3: combine split-K partials + sum-pool over j ------
// grid 64 (atom i); 128 threads: tid = h*32 + d.
__global__ __launch_bounds__(128) void reduce_kernel(float* __restrict__ out) {
    const int i = blockIdx.x;
    const int tid = threadIdx.x;
    const int h = tid >> 5, d = tid & 31;

    __shared__ float swt[H * 64 * KSPLIT];   // normalized weights per (h, j, kc)

    // stage 1: per-(h,s) softmax-combine weights (no redundant MUFU per lane)
    for (int c = tid; c < H * 64; c += 128) {
        int hh = c >> 6, j = c & 63;
        int s = i * 64 + j;
        int base = (hh * S + s) * KSPLIT;
        float m[KSPLIT];
        float M = -NEGBIG;
        #pragma unroll
        for (int k = 0; k < KSPLIT; k++) { m[k] = g_pm[base + k]; M = fmaxf(M, m[k]); }
        float w[KSPLIT];
        float L = 0.0f;
        #pragma unroll
        for (int k = 0; k < KSPLIT; k++) {
            w[k] = __expf(m[k] - M);
            L += w[k] * g_pl[base + k];
        }
        float invL = 1.0f / L;
        #pragma unroll
        for (int k = 0; k < KSPLIT; k++) swt[c * KSPLIT + k] = w[k] * invL;
    }
    __syncthreads();

    // stage 2: out[i][h*32+d] = sum_j sum_kc w * po
    float acc = 0.0f;
    for (int j = 0; j < 64; j++) {
        int s = i * 64 + j;
        int base = (h * S + s) * KSPLIT;
        #pragma unroll
        for (int k = 0; k < KSPLIT; k++) {
            acc += swt[((h * 64 + j) * KSPLIT) + k] * g_po[(size_t)(base + k) * D + d];
        }
    }
    out[i * HD + tid] = acc;
}

// ---------------- launch ----------------------------------------------------
extern "C" void kernel_launch(void* const* d_in, const int* in_sizes, int n_in,
                              void* d_out, int out_size) {
    const float* x    = (const float*)d_in[0];  // pair_features (64,64,128)
    const int*   mask = (const int*)  d_in[1];  // atom_mask (64,)
    const float* Wq   = (const float*)d_in[2];
    const float* bq   = (const float*)d_in[3];
    const float* Wk   = (const float*)d_in[4];
    const float* bk   = (const float*)d_in[5];
    const float* Wv   = (const float*)d_in[6];
    const float* bv   = (const float*)d_in[7];
    float* out = (float*)d_out;

    bias_kernel<<<4, 1024>>>(mask);
    proj_kernel<<<dim3(S / 32, 3), 256>>>(x, Wq, bq, Wk, bk, Wv, bv);
    attn_kernel<<<dim3(S / QB, H, KSPLIT), 128>>>();
    reduce_kernel<<<64, 128>>>(out);
}

// round 2
// speedup vs baseline: 1.2366x; 1.2366x over previous
#include <cuda_runtime.h>

#define S        4096
#define D_IN     128
#define H        4
#define D        32
#define HD       128
#define KSPLIT   8
#define KEYS_PER_SPLIT (S / KSPLIT)   // 512
#define KT       64                    // key tile in smem
#define QB       256                   // queries per attention block (128 thr * 2)
#define NEGBIG   1e30f
// scale * log2(e): fold into q so p = 2^(q.k + bias)
#define QSCALE   (0.17677669529663687f * 1.4426950408889634f)

// ---------------- scratch (device globals: no allocations allowed) ----------
__device__ float g_q[H * S * D];            // (h, s, d) -- pre-scaled by QSCALE
__device__ float g_k[H * S * D];
__device__ float g_v[H * S * D];
__device__ float g_bias[S];                 // 0 or -1e30 (log2-domain safe)
__device__ float g_pl[H * S * KSPLIT];      // partial sum-exp2
__device__ float g_po[H * S * KSPLIT * D];  // partial (unnormalized) output

// ---------------- packed f32x2 math (2x FFMA throughput, PTX-only) ----------
__device__ __forceinline__ float2 ffma2(float2 a, float2 b, float2 c) {
    float2 r;
    asm("fma.rn.f32x2 %0, %1, %2, %3;"
        : "=l"(*reinterpret_cast<unsigned long long*>(&r))
        : "l"(*reinterpret_cast<unsigned long long*>(&a)),
          "l"(*reinterpret_cast<unsigned long long*>(&b)),
          "l"(*reinterpret_cast<unsigned long long*>(&c)));
    return r;
}
__device__ __forceinline__ float ex2(float x) {
    float r;
    asm("ex2.approx.f32 %0, %1;" : "=f"(r) : "f"(x));
    return r;
}

// ---------------- kernel 0: key-validity bias ------------------------------
__global__ void bias_kernel(const int* __restrict__ mask) {
    int t = blockIdx.x * blockDim.x + threadIdx.x;
    if (t < S) {
        int a = t >> 6, b = t & 63;
        g_bias[t] = (mask[a] && mask[b]) ? 0.0f : -NEGBIG;
    }
}

// ---------------- kernel 1: fused QKV projection (tiled GEMM, f32x2) --------
// grid (S/32, 3): blockIdx.y selects Wq/Wk/Wv.  Block: 256 thr, 32 rows x 128 cols.
__global__ __launch_bounds__(256) void proj_kernel(
    const float* __restrict__ x,
    const float* __restrict__ Wq, const float* __restrict__ bq,
    const float* __restrict__ Wk, const float* __restrict__ bk,
    const float* __restrict__ Wv, const float* __restrict__ bv) {

    const int rowbase = blockIdx.x * 32;
    const int proj = blockIdx.y;
    const float* W    = (proj == 0) ? Wq : (proj == 1) ? Wk : Wv;
    const float* bias = (proj == 0) ? bq : (proj == 1) ? bk : bv;
    float* out        = (proj == 0) ? g_q : (proj == 1) ? g_k : g_v;

    __shared__ float sx[32 * D_IN];   // 16 KB
    __shared__ float sw[32 * HD];     // 16 KB (k-slab of W)

    const int tid = threadIdx.x;

    {
        const float4* xg = (const float4*)(x + (size_t)rowbase * D_IN);
        float4* sx4 = (float4*)sx;
        #pragma unroll
        for (int i = 0; i < 4; i++) sx4[tid + i * 256] = xg[tid + i * 256];
    }

    const int ty = tid >> 4;   // 0..15 -> rows ty*2, ty*2+1
    const int tx = tid & 15;   // cols tx*8 .. tx*8+7

    float2 acc[2][4];
    #pragma unroll
    for (int r = 0; r < 2; r++)
        #pragma unroll
        for (int c = 0; c < 4; c++) acc[r][c] = make_float2(0.f, 0.f);

    for (int kk = 0; kk < 4; kk++) {
        __syncthreads();
        {
            const float4* wg = (const float4*)(W + (size_t)(kk * 32) * HD);
            float4* sw4 = (float4*)sw;
            #pragma unroll
            for (int i = 0; i < 4; i++) sw4[tid + i * 256] = wg[tid + i * 256];
        }
        __syncthreads();
        #pragma unroll
        for (int k = 0; k < 32; k++) {
            float2 x0 = make_float2(sx[(ty * 2 + 0) * D_IN + kk * 32 + k],
                                    sx[(ty * 2 + 0) * D_IN + kk * 32 + k]);
            float2 x1 = make_float2(sx[(ty * 2 + 1) * D_IN + kk * 32 + k],
                                    sx[(ty * 2 + 1) * D_IN + kk * 32 + k]);
            float4 w0 = *(const float4*)&sw[k * HD + tx * 8];
            float4 w1 = *(const float4*)&sw[k * HD + tx * 8 + 4];
            float2 wp[4] = {make_float2(w0.x, w0.y), make_float2(w0.z, w0.w),
                            make_float2(w1.x, w1.y), make_float2(w1.z, w1.w)};
            #pragma unroll
            for (int c = 0; c < 4; c++) {
                acc[0][c] = ffma2(x0, wp[c], acc[0][c]);
                acc[1][c] = ffma2(x1, wp[c], acc[1][c]);
            }
        }
    }

    const float oscale = (proj == 0) ? QSCALE : 1.0f;
    #pragma unroll
    for (int r = 0; r < 2; r++) {
        int row = rowbase + ty * 2 + r;
        #pragma unroll
        for (int c = 0; c < 4; c++) {
            int col0 = tx * 8 + c * 2;
            float v0 = (acc[r][c].x + bias[col0])     * oscale;
            float v1 = (acc[r][c].y + bias[col0 + 1]) * oscale;
            int h0 = col0 >> 5, d0 = col0 & 31;
            out[((size_t)h0 * S + row) * D + d0]     = v0;
            out[((size_t)h0 * S + row) * D + d0 + 1] = v1;
        }
    }
}

// ---------------- kernel 2: flash attention (fixed-max), split-K ------------
// grid (S/QB=16, H=4, KSPLIT=8) = 512 blocks; 128 threads; 2 queries/thread.
__global__ __launch_bounds__(128, 3) void attn_kernel() {
    const int qtile = blockIdx.x;
    const int h     = blockIdx.y;
    const int kc    = blockIdx.z;
    const int tid   = threadIdx.x;

    const int q0i = qtile * QB + tid;
    const int q1i = q0i + 128;

    __shared__ float sk[KT * D];      // 8 KB
    __shared__ float sv[KT * D];      // 8 KB
    __shared__ float sbias[KT];

    float2 q0p[16], q1p[16], o0p[16], o1p[16];
    {
        const float4* qg0 = (const float4*)(g_q + ((size_t)h * S + q0i) * D);
        const float4* qg1 = (const float4*)(g_q + ((size_t)h * S + q1i) * D);
        #pragma unroll
        for (int i = 0; i < 8; i++) {
            float4 a = qg0[i];
            q0p[2 * i]     = make_float2(a.x, a.y);
            q0p[2 * i + 1] = make_float2(a.z, a.w);
            float4 b = qg1[i];
            q1p[2 * i]     = make_float2(b.x, b.y);
            q1p[2 * i + 1] = make_float2(b.z, b.w);
            o0p[2 * i] = o0p[2 * i + 1] = make_float2(0.0f, 0.0f);
            o1p[2 * i] = o1p[2 * i + 1] = make_float2(0.0f, 0.0f);
        }
    }
    float l0 = 0.0f, l1 = 0.0f;

    const int kbase = kc * KEYS_PER_SPLIT;

    for (int jt = 0; jt < KEYS_PER_SPLIT / KT; jt++) {   // 8 tiles
        __syncthreads();
        {
            const float4* kg = (const float4*)(g_k + ((size_t)h * S + kbase + jt * KT) * D);
            const float4* vg = (const float4*)(g_v + ((size_t)h * S + kbase + jt * KT) * D);
            float4* sk4 = (float4*)sk;
            float4* sv4 = (float4*)sv;
            #pragma unroll
            for (int i = 0; i < 4; i++) {
                sk4[tid + i * 128] = kg[tid + i * 128];
                sv4[tid + i * 128] = vg[tid + i * 128];
            }
            if (tid < KT) sbias[tid] = g_bias[kbase + jt * KT + tid];
        }
        __syncthreads();

        #pragma unroll 2
        for (int t = 0; t < KT; t++) {
            // --- scores (q pre-scaled by scale*log2e) ---
            const float4* kp = (const float4*)(sk + t * D);
            float2 a0 = make_float2(0.f, 0.f), b0 = make_float2(0.f, 0.f);
            float2 a1 = make_float2(0.f, 0.f), b1 = make_float2(0.f, 0.f);
            #pragma unroll
            for (int i = 0; i < 8; i++) {
                float4 kk = kp[i];
                float2 klo = make_float2(kk.x, kk.y);
                float2 khi = make_float2(kk.z, kk.w);
                a0 = ffma2(q0p[2 * i],     klo, a0);
                b0 = ffma2(q0p[2 * i + 1], khi, b0);
                a1 = ffma2(q1p[2 * i],     klo, a1);
                b1 = ffma2(q1p[2 * i + 1], khi, b1);
            }
            float bias_t = sbias[t];
            float s0 = (a0.x + b0.x) + (a0.y + b0.y) + bias_t;
            float s1 = (a1.x + b1.x) + (a1.y + b1.y) + bias_t;

            // --- fixed-max softmax numerator (scores bounded; masked -> 0) ---
            float p0 = ex2(s0);
            float p1 = ex2(s1);
            l0 += p0;
            l1 += p1;

            // --- o += p * v ---
            const float4* vp = (const float4*)(sv + t * D);
            float2 p02 = make_float2(p0, p0), p12 = make_float2(p1, p1);
            #pragma unroll
            for (int i = 0; i < 8; i++) {
                float4 vv = vp[i];
                float2 vlo = make_float2(vv.x, vv.y);
                float2 vhi = make_float2(vv.z, vv.w);
                o0p[2 * i]     = ffma2(p02, vlo, o0p[2 * i]);
                o0p[2 * i + 1] = ffma2(p02, vhi, o0p[2 * i + 1]);
                o1p[2 * i]     = ffma2(p12, vlo, o1p[2 * i]);
                o1p[2 * i + 1] = ffma2(p12, vhi, o1p[2 * i + 1]);
            }
        }
    }

    // --- write partials (linear combine: plain sums downstream) ---
    int prow0 = ((h * S) + q0i) * KSPLIT + kc;
    int prow1 = ((h * S) + q1i) * KSPLIT + kc;
    g_pl[prow0] = l0;
    g_pl[prow1] = l1;
    float4* po0 = (float4*)(g_po + (size_t)prow0 * D);
    float4* po1 = (float4*)(g_po + (size_t)prow1 * D);
    #pragma unroll
    for (int i = 0; i < 8; i++) {
        po0[i] = make_float4(o0p[2 * i].x, o0p[2 * i].y, o0p[2 * i + 1].x, o0p[2 * i + 1].y);
        po1[i] = make_float4(o1p[2 * i].x, o1p[2 * i].y, o1p[2 * i + 1].x, o1p[2 * i + 1].y);
    }
}

// ---------------- kernel 3: combine split-K + sum-pool over j ---------------
// grid (64, H) = 256 blocks; 128 threads: jg = tid>>5 (4 j-groups), d = tid&31.
__global__ __launch_bounds__(128) void reduce_kernel(float* __restrict__ out) {
    const int i = blockIdx.x;
    const int h = blockIdx.y;
    const int tid = threadIdx.x;
    const int jg = tid >> 5;
    const int d  = tid & 31;

    __shared__ float sinvL[64];
    __shared__ float sacc[128];

    if (tid < 64) {
        int s = i * 64 + tid;
        int base = (h * S + s) * KSPLIT;
        float L = 0.0f;
        #pragma unroll
        for (int k = 0; k < KSPLIT; k++) L += g_pl[base + k];
        sinvL[tid] = 1.0f / L;
    }
    __syncthreads();

    float acc = 0.0f;
    #pragma unroll 4
    for (int jj = 0; jj < 16; jj++) {
        int j = jg * 16 + jj;
        int s = i * 64 + j;
        size_t base = ((size_t)(h * S + s) * KSPLIT) * D + d;
        float o = 0.0f;
        #pragma unroll
        for (int k = 0; k < KSPLIT; k++) o += g_po[base + (size_t)k * D];
        acc += o * sinvL[j];
    }

    sacc[tid] = acc;
    __syncthreads();
    if (tid < 32) {
        float r = sacc[tid] + sacc[tid + 32] + sacc[tid + 64] + sacc[tid + 96];
        out[i * HD + h * 32 + tid] = r;
    }
}

// ---------------- launch ----------------------------------------------------
extern "C" void kernel_launch(void* const* d_in, const int* in_sizes, int n_in,
                              void* d_out, int out_size) {
    const float* x    = (const float*)d_in[0];  // pair_features (64,64,128)
    const int*   mask = (const int*)  d_in[1];  // atom_mask (64,)
    const float* Wq   = (const float*)d_in[2];
    const float* bq   = (const float*)d_in[3];
    const float* Wk   = (const float*)d_in[4];
    const float* bk   = (const float*)d_in[5];
    const float* Wv   = (const float*)d_in[6];
    const float* bv   = (const float*)d_in[7];
    float* out = (float*)d_out;

    bias_kernel<<<4, 1024>>>(mask);
    proj_kernel<<<dim3(S / 32, 3), 256>>>(x, Wq, bq, Wk, bk, Wv, bv);
    attn_kernel<<<dim3(S / QB, H, KSPLIT), 128>>>();
    reduce_kernel<<<dim3(64, H), 128>>>(out);
}

// round 3
// speedup vs baseline: 2.6245x; 2.1223x over previous
#include <cuda_runtime.h>
#include <cstdint>

#define S        4096
#define D_IN     128
#define H        4
#define D        32
#define HD       128
#define KSPLIT   2
#define KEYS_PER_SPLIT (S / KSPLIT)   // 2048
#define KT       128                   // key tile in smem
#define QT       128                   // queries per block (8 warps * 16)
#define NEGBIG   1e30f
// scale * log2(e): fold into q so p = 2^(q.k + bias)
#define QSCALE   (0.17677669529663687f * 1.4426950408889634f)
#define SK_STRIDE 36                   // floats per K row (conflict-free B-frag)
#define SV_STRIDE 40                   // floats per V row (conflict-free B-frag)

// ---------------- scratch (device globals: no allocations allowed) ----------
__device__ float g_q[H * S * D];            // (h, s, d) -- pre-scaled by QSCALE
__device__ float g_k[H * S * D];
__device__ float g_v[H * S * D];
__device__ float g_bias[S];                 // 0 or -1e30
__device__ float g_pl[H * S * KSPLIT];      // partial sum-exp2
__device__ float g_po[H * S * KSPLIT * D];  // partial (unnormalized) output

// ---------------- helpers ----------------------------------------------------
__device__ __forceinline__ float2 ffma2(float2 a, float2 b, float2 c) {
    float2 r;
    asm("fma.rn.f32x2 %0, %1, %2, %3;"
        : "=l"(*reinterpret_cast<unsigned long long*>(&r))
        : "l"(*reinterpret_cast<unsigned long long*>(&a)),
          "l"(*reinterpret_cast<unsigned long long*>(&b)),
          "l"(*reinterpret_cast<unsigned long long*>(&c)));
    return r;
}
__device__ __forceinline__ float ex2(float x) {
    float r;
    asm("ex2.approx.f32 %0, %1;" : "=f"(r) : "f"(x));
    return r;
}
__device__ __forceinline__ uint32_t tf32_of(float f) {
    uint32_t u;
    asm("cvt.rna.tf32.f32 %0, %1;" : "=r"(u) : "f"(f));
    return u;
}
__device__ __forceinline__ void mma_tf32(float& d0, float& d1, float& d2, float& d3,
                                         uint32_t a0, uint32_t a1, uint32_t a2, uint32_t a3,
                                         uint32_t b0, uint32_t b1) {
    asm("mma.sync.aligned.m16n8k8.row.col.f32.tf32.tf32.f32 "
        "{%0,%1,%2,%3}, {%4,%5,%6,%7}, {%8,%9}, {%0,%1,%2,%3};"
        : "+f"(d0), "+f"(d1), "+f"(d2), "+f"(d3)
        : "r"(a0), "r"(a1), "r"(a2), "r"(a3), "r"(b0), "r"(b1));
}

// ---------------- kernel 0: key-validity bias ------------------------------
__global__ void bias_kernel(const int* __restrict__ mask) {
    int t = blockIdx.x * blockDim.x + threadIdx.x;
    if (t < S) {
        int a = t >> 6, b = t & 63;
        g_bias[t] = (mask[a] && mask[b]) ? 0.0f : -NEGBIG;
    }
}

// ---------------- kernel 1: fused QKV projection (tiled GEMM, f32x2) --------
__global__ __launch_bounds__(256) void proj_kernel(
    const float* __restrict__ x,
    const float* __restrict__ Wq, const float* __restrict__ bq,
    const float* __restrict__ Wk, const float* __restrict__ bk,
    const float* __restrict__ Wv, const float* __restrict__ bv) {

    const int rowbase = blockIdx.x * 32;
    const int proj = blockIdx.y;
    const float* W    = (proj == 0) ? Wq : (proj == 1) ? Wk : Wv;
    const float* bias = (proj == 0) ? bq : (proj == 1) ? bk : bv;
    float* out        = (proj == 0) ? g_q : (proj == 1) ? g_k : g_v;

    __shared__ float sx[32 * D_IN];
    __shared__ float sw[32 * HD];

    const int tid = threadIdx.x;
    {
        const float4* xg = (const float4*)(x + (size_t)rowbase * D_IN);
        float4* sx4 = (float4*)sx;
        #pragma unroll
        for (int i = 0; i < 4; i++) sx4[tid + i * 256] = xg[tid + i * 256];
    }

    const int ty = tid >> 4;
    const int tx = tid & 15;

    float2 acc[2][4];
    #pragma unroll
    for (int r = 0; r < 2; r++)
        #pragma unroll
        for (int c = 0; c < 4; c++) acc[r][c] = make_float2(0.f, 0.f);

    for (int kk = 0; kk < 4; kk++) {
        __syncthreads();
        {
            const float4* wg = (const float4*)(W + (size_t)(kk * 32) * HD);
            float4* sw4 = (float4*)sw;
            #pragma unroll
            for (int i = 0; i < 4; i++) sw4[tid + i * 256] = wg[tid + i * 256];
        }
        __syncthreads();
        #pragma unroll
        for (int k = 0; k < 32; k++) {
            float x0s = sx[(ty * 2 + 0) * D_IN + kk * 32 + k];
            float x1s = sx[(ty * 2 + 1) * D_IN + kk * 32 + k];
            float2 x0 = make_float2(x0s, x0s);
            float2 x1 = make_float2(x1s, x1s);
            float4 w0 = *(const float4*)&sw[k * HD + tx * 8];
            float4 w1 = *(const float4*)&sw[k * HD + tx * 8 + 4];
            float2 wp[4] = {make_float2(w0.x, w0.y), make_float2(w0.z, w0.w),
                            make_float2(w1.x, w1.y), make_float2(w1.z, w1.w)};
            #pragma unroll
            for (int c = 0; c < 4; c++) {
                acc[0][c] = ffma2(x0, wp[c], acc[0][c]);
                acc[1][c] = ffma2(x1, wp[c], acc[1][c]);
            }
        }
    }

    const float oscale = (proj == 0) ? QSCALE : 1.0f;
    #pragma unroll
    for (int r = 0; r < 2; r++) {
        int row = rowbase + ty * 2 + r;
        #pragma unroll
        for (int c = 0; c < 4; c++) {
            int col0 = tx * 8 + c * 2;
            float v0 = (acc[r][c].x + bias[col0])     * oscale;
            float v1 = (acc[r][c].y + bias[col0 + 1]) * oscale;
            int h0 = col0 >> 5, d0 = col0 & 31;
            out[((size_t)h0 * S + row) * D + d0]     = v0;
            out[((size_t)h0 * S + row) * D + d0 + 1] = v1;
        }
    }
}

// ---------------- kernel 2: tf32 tensor-core flash attention ----------------
// grid (S/QT=32, H=4, KSPLIT=2) = 256 blocks; 256 threads = 8 warps.
// Each warp owns 16 query rows; block streams KT=128-key tiles through smem.
__global__ __launch_bounds__(256, 2) void attn_kernel() {
    const int qtile = blockIdx.x;
    const int h     = blockIdx.y;
    const int kc    = blockIdx.z;
    const int tid   = threadIdx.x;
    const int warp  = tid >> 5;
    const int lane  = tid & 31;
    const int gid   = lane >> 2;   // group id 0..7
    const int tig   = lane & 3;    // thread in group

    __shared__ __align__(16) uint32_t sk[KT * SK_STRIDE];   // tf32 K tile
    __shared__ __align__(16) uint32_t sv[KT * SV_STRIDE];   // tf32 V tile
    __shared__ float sbias[KT];

    const int q0 = qtile * QT + warp * 16 + gid;   // rows gid, gid+8 of m16
    const int q1 = q0 + 8;

    // Q fragments (held for whole kernel), tf32
    uint32_t qa[4][4];
    #pragma unroll
    for (int ks = 0; ks < 4; ks++) {
        const float* q0p = g_q + ((size_t)h * S + q0) * D + ks * 8;
        const float* q1p = g_q + ((size_t)h * S + q1) * D + ks * 8;
        qa[ks][0] = tf32_of(q0p[tig]);
        qa[ks][1] = tf32_of(q1p[tig]);
        qa[ks][2] = tf32_of(q0p[tig + 4]);
        qa[ks][3] = tf32_of(q1p[tig + 4]);
    }

    float o[4][4];
    #pragma unroll
    for (int nc = 0; nc < 4; nc++)
        #pragma unroll
        for (int r = 0; r < 4; r++) o[nc][r] = 0.0f;
    float l0 = 0.0f, l1 = 0.0f;

    const int kbase = kc * KEYS_PER_SPLIT;
    const unsigned FULL = 0xffffffffu;

    for (int jt = 0; jt < KEYS_PER_SPLIT / KT; jt++) {   // 16 tiles
        __syncthreads();
        {   // fill K/V tiles (convert fp32 -> tf32 at store)
            const float4* kg = (const float4*)(g_k + ((size_t)h * S + kbase + jt * KT) * D);
            const float4* vg = (const float4*)(g_v + ((size_t)h * S + kbase + jt * KT) * D);
            #pragma unroll
            for (int i = 0; i < 4; i++) {
                int idx = tid + i * 256;        // 0..1023 float4s (128 rows x 8)
                int row = idx >> 3, c4 = idx & 7;
                float4 kvx = kg[idx];
                uint32_t* kd = &sk[row * SK_STRIDE + c4 * 4];
                kd[0] = tf32_of(kvx.x); kd[1] = tf32_of(kvx.y);
                kd[2] = tf32_of(kvx.z); kd[3] = tf32_of(kvx.w);
                float4 vvx = vg[idx];
                uint32_t* vd = &sv[row * SV_STRIDE + c4 * 4];
                vd[0] = tf32_of(vvx.x); vd[1] = tf32_of(vvx.y);
                vd[2] = tf32_of(vvx.z); vd[3] = tf32_of(vvx.w);
            }
            if (tid < KT) sbias[tid] = g_bias[kbase + jt * KT + tid];
        }
        __syncthreads();

        #pragma unroll 1
        for (int kg8 = 0; kg8 < KT / 8; kg8++) {      // 16 chunks of 8 keys
            // ---- QK^T: S(16x8) = sum_ks Q_ks @ K_ks ----
            float c0 = 0.f, c1 = 0.f, c2 = 0.f, c3 = 0.f;
            #pragma unroll
            for (int ks = 0; ks < 4; ks++) {
                uint32_t b0 = sk[(kg8 * 8 + gid) * SK_STRIDE + ks * 8 + tig];
                uint32_t b1 = sk[(kg8 * 8 + gid) * SK_STRIDE + ks * 8 + tig + 4];
                mma_tf32(c0, c1, c2, c3, qa[ks][0], qa[ks][1], qa[ks][2], qa[ks][3], b0, b1);
            }
            float2 b2 = ((const float2*)sbias)[kg8 * 4 + tig];

            // ---- fixed-max softmax numerator (log2 domain) ----
            float p0 = ex2(c0 + b2.x), p1 = ex2(c1 + b2.y);
            float p2 = ex2(c2 + b2.x), p3 = ex2(c3 + b2.y);
            uint32_t u0 = tf32_of(p0), u1 = tf32_of(p1);
            uint32_t u2 = tf32_of(p2), u3 = tf32_of(p3);
            l0 += __uint_as_float(u0) + __uint_as_float(u1);
            l1 += __uint_as_float(u2) + __uint_as_float(u3);

            // ---- relayout P (C-frag cols {2tig,2tig+1}) -> A-frag cols {tig,tig+4} ----
            int base = lane & ~3;
            int s0 = base + (tig >> 1);
            int s1 = base + 2 + (tig >> 1);
            bool odd = (tig & 1);
            uint32_t v00 = __shfl_sync(FULL, u0, s0), v01 = __shfl_sync(FULL, u1, s0);
            uint32_t v10 = __shfl_sync(FULL, u2, s0), v11 = __shfl_sync(FULL, u3, s0);
            uint32_t w00 = __shfl_sync(FULL, u0, s1), w01 = __shfl_sync(FULL, u1, s1);
            uint32_t w10 = __shfl_sync(FULL, u2, s1), w11 = __shfl_sync(FULL, u3, s1);
            uint32_t pa0 = odd ? v01 : v00;   // P[gid  ][tig]
            uint32_t pa1 = odd ? v11 : v10;   // P[gid+8][tig]
            uint32_t pa2 = odd ? w01 : w00;   // P[gid  ][tig+4]
            uint32_t pa3 = odd ? w11 : w10;   // P[gid+8][tig+4]

            // ---- PV: O(16x32) += P(16x8) @ V(8x32), 4 n-chunks ----
            #pragma unroll
            for (int nc = 0; nc < 4; nc++) {
                uint32_t b0 = sv[(kg8 * 8 + tig)     * SV_STRIDE + nc * 8 + gid];
                uint32_t b1 = sv[(kg8 * 8 + tig + 4) * SV_STRIDE + nc * 8 + gid];
                mma_tf32(o[nc][0], o[nc][1], o[nc][2], o[nc][3],
                         pa0, pa1, pa2, pa3, b0, b1);
            }
        }
    }

    // ---- reduce l across the 4 threads of each group ----
    l0 += __shfl_xor_sync(FULL, l0, 1); l0 += __shfl_xor_sync(FULL, l0, 2);
    l1 += __shfl_xor_sync(FULL, l1, 1); l1 += __shfl_xor_sync(FULL, l1, 2);

    const int prow0 = ((h * S) + q0) * KSPLIT + kc;
    const int prow1 = ((h * S) + q1) * KSPLIT + kc;
    if (tig == 0) { g_pl[prow0] = l0; g_pl[prow1] = l1; }

    float2* po0 = (float2*)(g_po + (size_t)prow0 * D);
    float2* po1 = (float2*)(g_po + (size_t)prow1 * D);
    #pragma unroll
    for (int nc = 0; nc < 4; nc++) {
        po0[nc * 4 + tig] = make_float2(o[nc][0], o[nc][1]);   // d = nc*8 + 2tig
        po1[nc * 4 + tig] = make_float2(o[nc][2], o[nc][3]);
    }
}

// ---------------- kernel 3: combine split-K + sum-pool over j ---------------
__global__ __launch_bounds__(128) void reduce_kernel(float* __restrict__ out) {
    const int i = blockIdx.x;
    const int h = blockIdx.y;
    const int tid = threadIdx.x;
    const int jg = tid >> 5;
    const int d  = tid & 31;

    __shared__ float sinvL[64];
    __shared__ float sacc[128];

    if (tid < 64) {
        int s = i * 64 + tid;
        int base = (h * S + s) * KSPLIT;
        float L = 0.0f;
        #pragma unroll
        for (int k = 0; k < KSPLIT; k++) L += g_pl[base + k];
        sinvL[tid] = 1.0f / L;
    }
    __syncthreads();

    float acc = 0.0f;
    #pragma unroll 4
    for (int jj = 0; jj < 16; jj++) {
        int j = jg * 16 + jj;
        int s = i * 64 + j;
        size_t base = ((size_t)(h * S + s) * KSPLIT) * D + d;
        float ov = 0.0f;
        #pragma unroll
        for (int k = 0; k < KSPLIT; k++) ov += g_po[base + (size_t)k * D];
        acc += ov * sinvL[j];
    }

    sacc[tid] = acc;
    __syncthreads();
    if (tid < 32) {
        float r = sacc[tid] + sacc[tid + 32] + sacc[tid + 64] + sacc[tid + 96];
        out[i * HD + h * 32 + tid] = r;
    }
}

// ---------------- launch ----------------------------------------------------
extern "C" void kernel_launch(void* const* d_in, const int* in_sizes, int n_in,
                              void* d_out, int out_size) {
    const float* x    = (const float*)d_in[0];
    const int*   mask = (const int*)  d_in[1];
    const float* Wq   = (const float*)d_in[2];
    const float* bq   = (const float*)d_in[3];
    const float* Wk   = (const float*)d_in[4];
    const float* bk   = (const float*)d_in[5];
    const float* Wv   = (const float*)d_in[6];
    const float* bv   = (const float*)d_in[7];
    float* out = (float*)d_out;

    bias_kernel<<<4, 1024>>>(mask);
    proj_kernel<<<dim3(S / 32, 3), 256>>>(x, Wq, bq, Wk, bk, Wv, bv);
    attn_kernel<<<dim3(S / QT, H, KSPLIT), 256>>>();
    reduce_kernel<<<dim3(64, H), 128>>>(out);
}

// round 4
// speedup vs baseline: 2.7116x; 1.0332x over previous
#include <cuda_runtime.h>
#include <cstdint>

#define S        4096
#define D_IN     128
#define H        4
#define D        32
#define HD       128
#define KSPLIT   4
#define KEYS_PER_SPLIT (S / KSPLIT)   // 1024
#define KT       128                   // key tile in smem
#define QT       256                   // queries per attention block (8 warps * 32)
#define NEGBIG   1e30f
#define QSCALE   (0.17677669529663687f * 1.4426950408889634f)  // scale*log2e

#define SK_STRIDE 36                   // dwords per K row
#define SV_ROWSTR 72                   // dwords per V tig-row (pair-packed), ==8 mod 32
#define SV_CHSTR  290                  // dwords per V chunk (4*72 + 2 pad)

// ---------------- scratch ----------------------------------------------------
__device__ float g_q[H * S * D];            // tf32 bits, pre-scaled by QSCALE
__device__ float g_k[H * S * D];            // tf32 bits
__device__ float g_v[H * S * D];            // tf32 bits
__device__ float g_bias[S];                 // 0 or -1e30
__device__ float g_pl[H * S * KSPLIT];
__device__ float g_po[H * S * KSPLIT * D];

// ---------------- helpers ----------------------------------------------------
__device__ __forceinline__ float2 ffma2(float2 a, float2 b, float2 c) {
    float2 r;
    asm("fma.rn.f32x2 %0, %1, %2, %3;"
        : "=l"(*reinterpret_cast<unsigned long long*>(&r))
        : "l"(*reinterpret_cast<unsigned long long*>(&a)),
          "l"(*reinterpret_cast<unsigned long long*>(&b)),
          "l"(*reinterpret_cast<unsigned long long*>(&c)));
    return r;
}
__device__ __forceinline__ float ex2(float x) {
    float r;
    asm("ex2.approx.f32 %0, %1;" : "=f"(r) : "f"(x));
    return r;
}
__device__ __forceinline__ uint32_t tf32_of(float f) {
    uint32_t u;
    asm("cvt.rna.tf32.f32 %0, %1;" : "=r"(u) : "f"(f));
    return u;
}
__device__ __forceinline__ void mma_tf32(float& d0, float& d1, float& d2, float& d3,
                                         uint32_t a0, uint32_t a1, uint32_t a2, uint32_t a3,
                                         uint32_t b0, uint32_t b1) {
    asm("mma.sync.aligned.m16n8k8.row.col.f32.tf32.tf32.f32 "
        "{%0,%1,%2,%3}, {%4,%5,%6,%7}, {%8,%9}, {%0,%1,%2,%3};"
        : "+f"(d0), "+f"(d1), "+f"(d2), "+f"(d3)
        : "r"(a0), "r"(a1), "r"(a2), "r"(a3), "r"(b0), "r"(b1));
}

// ---------------- kernel 0: key-validity bias ------------------------------
__global__ void bias_kernel(const int* __restrict__ mask) {
    int t = blockIdx.x * blockDim.x + threadIdx.x;
    if (t < S) {
        int a = t >> 6, b = t & 63;
        g_bias[t] = (mask[a] && mask[b]) ? 0.0f : -NEGBIG;
    }
}

// ---------------- kernel 1: fused QKV projection (f32x2 + tf32 epilogue) ----
__global__ __launch_bounds__(256) void proj_kernel(
    const float* __restrict__ x,
    const float* __restrict__ Wq, const float* __restrict__ bq,
    const float* __restrict__ Wk, const float* __restrict__ bk,
    const float* __restrict__ Wv, const float* __restrict__ bv) {

    const int rowbase = blockIdx.x * 32;
    const int proj = blockIdx.y;
    const float* W    = (proj == 0) ? Wq : (proj == 1) ? Wk : Wv;
    const float* bias = (proj == 0) ? bq : (proj == 1) ? bk : bv;
    float* out        = (proj == 0) ? g_q : (proj == 1) ? g_k : g_v;

    __shared__ float sx[32 * D_IN];
    __shared__ float sw[32 * HD];

    const int tid = threadIdx.x;
    {
        const float4* xg = (const float4*)(x + (size_t)rowbase * D_IN);
        float4* sx4 = (float4*)sx;
        #pragma unroll
        for (int i = 0; i < 4; i++) sx4[tid + i * 256] = xg[tid + i * 256];
    }

    const int ty = tid >> 4;
    const int tx = tid & 15;

    float2 acc[2][4];
    #pragma unroll
    for (int r = 0; r < 2; r++)
        #pragma unroll
        for (int c = 0; c < 4; c++) acc[r][c] = make_float2(0.f, 0.f);

    for (int kk = 0; kk < 4; kk++) {
        __syncthreads();
        {
            const float4* wg = (const float4*)(W + (size_t)(kk * 32) * HD);
            float4* sw4 = (float4*)sw;
            #pragma unroll
            for (int i = 0; i < 4; i++) sw4[tid + i * 256] = wg[tid + i * 256];
        }
        __syncthreads();
        #pragma unroll
        for (int k = 0; k < 32; k++) {
            float x0s = sx[(ty * 2 + 0) * D_IN + kk * 32 + k];
            float x1s = sx[(ty * 2 + 1) * D_IN + kk * 32 + k];
            float2 x0 = make_float2(x0s, x0s);
            float2 x1 = make_float2(x1s, x1s);
            float4 w0 = *(const float4*)&sw[k * HD + tx * 8];
            float4 w1 = *(const float4*)&sw[k * HD + tx * 8 + 4];
            float2 wp[4] = {make_float2(w0.x, w0.y), make_float2(w0.z, w0.w),
                            make_float2(w1.x, w1.y), make_float2(w1.z, w1.w)};
            #pragma unroll
            for (int c = 0; c < 4; c++) {
                acc[0][c] = ffma2(x0, wp[c], acc[0][c]);
                acc[1][c] = ffma2(x1, wp[c], acc[1][c]);
            }
        }
    }

    const float oscale = (proj == 0) ? QSCALE : 1.0f;
    #pragma unroll
    for (int r = 0; r < 2; r++) {
        int row = rowbase + ty * 2 + r;
        #pragma unroll
        for (int c = 0; c < 4; c++) {
            int col0 = tx * 8 + c * 2;
            float v0 = (acc[r][c].x + bias[col0])     * oscale;
            float v1 = (acc[r][c].y + bias[col0 + 1]) * oscale;
            int h0 = col0 >> 5, d0 = col0 & 31;
            out[((size_t)h0 * S + row) * D + d0]     = __uint_as_float(tf32_of(v0));
            out[((size_t)h0 * S + row) * D + d0 + 1] = __uint_as_float(tf32_of(v1));
        }
    }
}

// ---------------- kernel 2: tf32 tensor-core flash attention ----------------
// grid (16, H, KSPLIT) = 256 blocks; 256 threads = 8 warps; 32 queries/warp.
__global__ __launch_bounds__(256, 2) void attn_kernel() {
    const int qtile = blockIdx.x;
    const int h     = blockIdx.y;
    const int kc    = blockIdx.z;
    const int tid   = threadIdx.x;
    const int warp  = tid >> 5;
    const int lane  = tid & 31;
    const int gid   = lane >> 2;
    const int tig   = lane & 3;

    __shared__ __align__(16) uint32_t sk[KT * SK_STRIDE];        // 18.0 KB
    __shared__ __align__(16) uint32_t sv[(KT / 8) * SV_CHSTR];   // 18.1 KB
    __shared__ float sbias[KT];

    const int qbase = qtile * QT + warp * 32;

    // Q fragments for 2 tiles (rows: t*16 + {gid, gid+8}); already tf32+scaled.
    uint32_t qa[2][4][4];
    #pragma unroll
    for (int t = 0; t < 2; t++) {
        const uint32_t* r0 = (const uint32_t*)(g_q + ((size_t)h * S + qbase + t * 16 + gid) * D);
        const uint32_t* r1 = (const uint32_t*)(g_q + ((size_t)h * S + qbase + t * 16 + gid + 8) * D);
        #pragma unroll
        for (int ks = 0; ks < 4; ks++) {
            qa[t][ks][0] = r0[ks * 8 + tig];
            qa[t][ks][1] = r1[ks * 8 + tig];
            qa[t][ks][2] = r0[ks * 8 + tig + 4];
            qa[t][ks][3] = r1[ks * 8 + tig + 4];
        }
    }

    float o[2][4][4];
    #pragma unroll
    for (int t = 0; t < 2; t++)
        #pragma unroll
        for (int nc = 0; nc < 4; nc++)
            #pragma unroll
            for (int r = 0; r < 4; r++) o[t][nc][r] = 0.0f;
    float l[2][2] = {{0.f, 0.f}, {0.f, 0.f}};

    const int kbase = kc * KEYS_PER_SPLIT;
    const unsigned FULL = 0xffffffffu;

    // fill-mapping constants
    const int kf_r  = tid & 7;            // K fill: row low bits
    const int kf_c4 = (tid >> 3) & 7;     //         float4 column
    const int kf_q  = tid >> 6;           //         row high
    const int kf_off = (kf_c4 >> 1) * 2 + (kf_c4 & 1);
    const int vf_row = (tid & 31) + 32 * (tid >> 6);  // V fill: one row per thread
    const int vf_c4b = (tid >> 5) & 1;
    const int vf_base = (vf_row >> 3) * SV_CHSTR + (vf_row & 3) * SV_ROWSTR + ((vf_row & 7) >> 2);

    for (int jt = 0; jt < KEYS_PER_SPLIT / KT; jt++) {   // 8 tiles
        __syncthreads();
        {
            const uint4* kg = (const uint4*)(g_k + ((size_t)h * S + kbase + jt * KT) * D);
            #pragma unroll
            for (int i = 0; i < 4; i++) {
                int row = kf_r + 8 * (kf_q + 4 * i);
                uint4 kv = kg[row * 8 + kf_c4];
                uint32_t* d = &sk[row * SK_STRIDE + kf_off];
                d[0]  = kv.x;  d[8]  = kv.y;  d[16] = kv.z;  d[24] = kv.w;
            }
            const uint4* vg = (const uint4*)(g_v + ((size_t)h * S + kbase + jt * KT) * D);
            #pragma unroll
            for (int i = 0; i < 4; i++) {
                int c4 = vf_c4b + 2 * i;
                uint4 vv = vg[vf_row * 8 + c4];
                uint32_t* d = &sv[vf_base + 8 * c4];   // 2*(4*c4)
                d[0] = vv.x;  d[2] = vv.y;  d[4] = vv.z;  d[6] = vv.w;
            }
            if (tid < KT) sbias[tid] = g_bias[kbase + jt * KT + tid];
        }
        __syncthreads();

        #pragma unroll 1
        for (int kg8 = 0; kg8 < KT / 8; kg8++) {      // 16 chunks of 8 keys
            // ---- K B-frags: 2x LDS.128 from permuted layout ----
            const uint32_t* kr = &sk[(kg8 * 8 + gid) * SK_STRIDE + tig * 8];
            uint4 kA = *(const uint4*)kr;
            uint4 kB = *(const uint4*)(kr + 4);

            // ---- QK^T for both q-tiles ----
            float c[2][4];
            #pragma unroll
            for (int t = 0; t < 2; t++) {
                c[t][0] = c[t][1] = c[t][2] = c[t][3] = 0.0f;
                mma_tf32(c[t][0], c[t][1], c[t][2], c[t][3],
                         qa[t][0][0], qa[t][0][1], qa[t][0][2], qa[t][0][3], kA.x, kA.y);
                mma_tf32(c[t][0], c[t][1], c[t][2], c[t][3],
                         qa[t][1][0], qa[t][1][1], qa[t][1][2], qa[t][1][3], kA.z, kA.w);
                mma_tf32(c[t][0], c[t][1], c[t][2], c[t][3],
                         qa[t][2][0], qa[t][2][1], qa[t][2][2], qa[t][2][3], kB.x, kB.y);
                mma_tf32(c[t][0], c[t][1], c[t][2], c[t][3],
                         qa[t][3][0], qa[t][3][1], qa[t][3][2], qa[t][3][3], kB.z, kB.w);
            }
            float2 b2 = ((const float2*)sbias)[kg8 * 4 + tig];

            // ---- softmax numerators + P relayout, per tile ----
            uint32_t pa[2][4];
            #pragma unroll
            for (int t = 0; t < 2; t++) {
                float p0 = ex2(c[t][0] + b2.x), p1 = ex2(c[t][1] + b2.y);
                float p2 = ex2(c[t][2] + b2.x), p3 = ex2(c[t][3] + b2.y);
                uint32_t u0 = tf32_of(p0), u1 = tf32_of(p1);
                uint32_t u2 = tf32_of(p2), u3 = tf32_of(p3);
                l[t][0] += __uint_as_float(u0) + __uint_as_float(u1);
                l[t][1] += __uint_as_float(u2) + __uint_as_float(u3);

                int base = lane & ~3;
                int s0 = base + (tig >> 1);
                int s1 = base + 2 + (tig >> 1);
                bool odd = (tig & 1);
                uint32_t v00 = __shfl_sync(FULL, u0, s0), v01 = __shfl_sync(FULL, u1, s0);
                uint32_t v10 = __shfl_sync(FULL, u2, s0), v11 = __shfl_sync(FULL, u3, s0);
                uint32_t w00 = __shfl_sync(FULL, u0, s1), w01 = __shfl_sync(FULL, u1, s1);
                uint32_t w10 = __shfl_sync(FULL, u2, s1), w11 = __shfl_sync(FULL, u3, s1);
                pa[t][0] = odd ? v01 : v00;
                pa[t][1] = odd ? v11 : v10;
                pa[t][2] = odd ? w01 : w00;
                pa[t][3] = odd ? w11 : w10;
            }

            // ---- PV: V B-frags shared across tiles (4x LDS.64) ----
            const uint32_t* vr = &sv[kg8 * SV_CHSTR + tig * SV_ROWSTR + 2 * gid];
            #pragma unroll
            for (int nc = 0; nc < 4; nc++) {
                uint2 vv = *(const uint2*)(vr + 16 * nc);
                mma_tf32(o[0][nc][0], o[0][nc][1], o[0][nc][2], o[0][nc][3],
                         pa[0][0], pa[0][1], pa[0][2], pa[0][3], vv.x, vv.y);
                mma_tf32(o[1][nc][0], o[1][nc][1], o[1][nc][2], o[1][nc][3],
                         pa[1][0], pa[1][1], pa[1][2], pa[1][3], vv.x, vv.y);
            }
        }
    }

    // ---- reduce l across the 4 threads of each group; write partials ----
    #pragma unroll
    for (int t = 0; t < 2; t++) {
        float l0 = l[t][0], l1 = l[t][1];
        l0 += __shfl_xor_sync(FULL, l0, 1); l0 += __shfl_xor_sync(FULL, l0, 2);
        l1 += __shfl_xor_sync(FULL, l1, 1); l1 += __shfl_xor_sync(FULL, l1, 2);

        const int q0 = qbase + t * 16 + gid;
        const int q1 = q0 + 8;
        const int prow0 = ((h * S) + q0) * KSPLIT + kc;
        const int prow1 = ((h * S) + q1) * KSPLIT + kc;
        if (tig == 0) { g_pl[prow0] = l0; g_pl[prow1] = l1; }

        float2* po0 = (float2*)(g_po + (size_t)prow0 * D);
        float2* po1 = (float2*)(g_po + (size_t)prow1 * D);
        #pragma unroll
        for (int nc = 0; nc < 4; nc++) {
            po0[nc * 4 + tig] = make_float2(o[t][nc][0], o[t][nc][1]);
            po1[nc * 4 + tig] = make_float2(o[t][nc][2], o[t][nc][3]);
        }
    }
}

// ---------------- kernel 3: combine split-K + sum-pool over j ---------------
__global__ __launch_bounds__(128) void reduce_kernel(float* __restrict__ out) {
    const int i = blockIdx.x;
    const int h = blockIdx.y;
    const int tid = threadIdx.x;
    const int jg = tid >> 5;
    const int d  = tid & 31;

    __shared__ float sinvL[64];
    __shared__ float sacc[128];

    if (tid < 64) {
        int s = i * 64 + tid;
        int base = (h * S + s) * KSPLIT;
        float L = 0.0f;
        #pragma unroll
        for (int k = 0; k < KSPLIT; k++) L += g_pl[base + k];
        sinvL[tid] = 1.0f / L;
    }
    __syncthreads();

    float acc = 0.0f;
    #pragma unroll 4
    for (int jj = 0; jj < 16; jj++) {
        int j = jg * 16 + jj;
        int s = i * 64 + j;
        size_t base = ((size_t)(h * S + s) * KSPLIT) * D + d;
        float ov = 0.0f;
        #pragma unroll
        for (int k = 0; k < KSPLIT; k++) ov += g_po[base + (size_t)k * D];
        acc += ov * sinvL[j];
    }

    sacc[tid] = acc;
    __syncthreads();
    if (tid < 32) {
        float r = sacc[tid] + sacc[tid + 32] + sacc[tid + 64] + sacc[tid + 96];
        out[i * HD + h * 32 + tid] = r;
    }
}

// ---------------- launch ----------------------------------------------------
extern "C" void kernel_launch(void* const* d_in, const int* in_sizes, int n_in,
                              void* d_out, int out_size) {
    const float* x    = (const float*)d_in[0];
    const int*   mask = (const int*)  d_in[1];
    const float* Wq   = (const float*)d_in[2];
    const float* bq   = (const float*)d_in[3];
    const float* Wk   = (const float*)d_in[4];
    const float* bk   = (const float*)d_in[5];
    const float* Wv   = (const float*)d_in[6];
    const float* bv   = (const float*)d_in[7];
    float* out = (float*)d_out;

    bias_kernel<<<4, 1024>>>(mask);
    proj_kernel<<<dim3(S / 32, 3), 256>>>(x, Wq, bq, Wk, bk, Wv, bv);
    attn_kernel<<<dim3(S / QT, H, KSPLIT), 256>>>();
    reduce_kernel<<<dim3(64, H), 128>>>(out);
}

// round 6
// speedup vs baseline: 4.2925x; 1.5830x over previous
#include <cuda_runtime.h>
#include <cuda_fp16.h>
#include <cstdint>

#define S        4096
#define D_IN     128
#define H        4
#define D        32
#define HD       128
#define KSPLIT   4
#define KEYS_PER_SPLIT (S / KSPLIT)   // 1024
#define KT       128                   // keys per smem tile
#define QT       256                   // queries per attention block (8 warps * 32)
#define NEGBIG   1e30f
#define QSCALE   (0.17677669529663687f * 1.4426950408889634f)  // scale*log2e

#define V_CHSTR  264                   // dwords per 16-key V chunk (256 + 8 pad)

// ---------------- scratch (fp16x2 packed, 16 dwords per row) ----------------
__device__ uint32_t g_q[H * S * 16];        // permuted cols, pre-scaled by QSCALE
__device__ uint32_t g_k[H * S * 16];        // permuted cols
__device__ uint32_t g_v[H * S * 16];        // plain d-pair packing
__device__ float g_bias[S];                 // 0 or -1e30
__device__ float g_pl[H * S * KSPLIT];
__device__ float g_po[H * S * KSPLIT * D];

// ---------------- helpers ----------------------------------------------------
__device__ __forceinline__ float2 ffma2(float2 a, float2 b, float2 c) {
    float2 r;
    asm("fma.rn.f32x2 %0, %1, %2, %3;"
        : "=l"(*reinterpret_cast<unsigned long long*>(&r))
        : "l"(*reinterpret_cast<unsigned long long*>(&a)),
          "l"(*reinterpret_cast<unsigned long long*>(&b)),
          "l"(*reinterpret_cast<unsigned long long*>(&c)));
    return r;
}
__device__ __forceinline__ float ex2(float x) {
    float r;
    asm("ex2.approx.f32 %0, %1;" : "=f"(r) : "f"(x));
    return r;
}
__device__ __forceinline__ uint32_t pack_h2(float lo, float hi) {
    __half2 h = __floats2half2_rn(lo, hi);       // x = lo bits, y = hi bits
    return *reinterpret_cast<uint32_t*>(&h);
}
__device__ __forceinline__ void mma16(float* d,
                                      uint32_t a0, uint32_t a1, uint32_t a2, uint32_t a3,
                                      uint32_t b0, uint32_t b1) {
    asm("mma.sync.aligned.m16n8k16.row.col.f32.f16.f16.f32 "
        "{%0,%1,%2,%3}, {%4,%5,%6,%7}, {%8,%9}, {%0,%1,%2,%3};"
        : "+f"(d[0]), "+f"(d[1]), "+f"(d[2]), "+f"(d[3])
        : "r"(a0), "r"(a1), "r"(a2), "r"(a3), "r"(b0), "r"(b1));
}

// ---------------- kernel 0: key-validity bias ------------------------------
__global__ void bias_kernel(const int* __restrict__ mask) {
    int t = blockIdx.x * blockDim.x + threadIdx.x;
    if (t < S) {
        int a = t >> 6, b = t & 63;
        g_bias[t] = (mask[a] && mask[b]) ? 0.0f : -NEGBIG;
    }
}

// ---------------- kernel 1: fused QKV projection (fp16 pack epilogue) -------
__global__ __launch_bounds__(256) void proj_kernel(
    const float* __restrict__ x,
    const float* __restrict__ Wq, const float* __restrict__ bq,
    const float* __restrict__ Wk, const float* __restrict__ bk,
    const float* __restrict__ Wv, const float* __restrict__ bv) {

    const int rowbase = blockIdx.x * 32;
    const int proj = blockIdx.y;
    const float* W    = (proj == 0) ? Wq : (proj == 1) ? Wk : Wv;
    const float* bias = (proj == 0) ? bq : (proj == 1) ? bk : bv;
    uint32_t* out     = (proj == 0) ? g_q : (proj == 1) ? g_k : g_v;

    __shared__ float sx[32 * D_IN];
    __shared__ float sw[32 * HD];

    const int tid = threadIdx.x;
    {
        const float4* xg = (const float4*)(x + (size_t)rowbase * D_IN);
        float4* sx4 = (float4*)sx;
        #pragma unroll
        for (int i = 0; i < 4; i++) sx4[tid + i * 256] = xg[tid + i * 256];
    }

    const int ty = tid >> 4;
    const int tx = tid & 15;

    float2 acc[2][4];
    #pragma unroll
    for (int r = 0; r < 2; r++)
        #pragma unroll
        for (int c = 0; c < 4; c++) acc[r][c] = make_float2(0.f, 0.f);

    for (int kk = 0; kk < 4; kk++) {
        __syncthreads();
        {
            const float4* wg = (const float4*)(W + (size_t)(kk * 32) * HD);
            float4* sw4 = (float4*)sw;
            #pragma unroll
            for (int i = 0; i < 4; i++) sw4[tid + i * 256] = wg[tid + i * 256];
        }
        __syncthreads();
        #pragma unroll
        for (int k = 0; k < 32; k++) {
            float x0s = sx[(ty * 2 + 0) * D_IN + kk * 32 + k];
            float x1s = sx[(ty * 2 + 1) * D_IN + kk * 32 + k];
            float2 x0 = make_float2(x0s, x0s);
            float2 x1 = make_float2(x1s, x1s);
            float4 w0 = *(const float4*)&sw[k * HD + tx * 8];
            float4 w1 = *(const float4*)&sw[k * HD + tx * 8 + 4];
            float2 wp[4] = {make_float2(w0.x, w0.y), make_float2(w0.z, w0.w),
                            make_float2(w1.x, w1.y), make_float2(w1.z, w1.w)};
            #pragma unroll
            for (int c = 0; c < 4; c++) {
                acc[0][c] = ffma2(x0, wp[c], acc[0][c]);
                acc[1][c] = ffma2(x1, wp[c], acc[1][c]);
            }
        }
    }

    const float oscale = (proj == 0) ? QSCALE : 1.0f;
    const bool permute = (proj != 2);   // Q and K get the MMA-fragment permutation
    #pragma unroll
    for (int r = 0; r < 2; r++) {
        int row = rowbase + ty * 2 + r;
        #pragma unroll
        for (int c = 0; c < 4; c++) {
            int col0 = tx * 8 + c * 2;
            float v0 = (acc[r][c].x + bias[col0])     * oscale;
            float v1 = (acc[r][c].y + bias[col0 + 1]) * oscale;
            int h0 = col0 >> 5;
            int d2 = (col0 & 31) >> 1;                 // d-pair index 0..15
            int p  = permute ? (((d2 & 3) << 2) | (d2 >> 2)) : d2;
            out[((size_t)h0 * S + row) * 16 + p] = pack_h2(v0, v1);
        }
    }
}

// ---------------- kernel 2: fp16 m16n8k16 flash attention -------------------
// grid (16, H, 4) = 256 blocks; 256 threads = 8 warps; 32 queries per warp.
__global__ __launch_bounds__(256, 2) void attn_kernel() {
    const int qtile = blockIdx.x;
    const int h     = blockIdx.y;
    const int kc    = blockIdx.z;
    const int tid   = threadIdx.x;
    const int warp  = tid >> 5;
    const int lane  = tid & 31;
    const int gid   = lane >> 2;
    const int tig   = lane & 3;

    __shared__ __align__(16) uint32_t sk[KT * 16];          // 8 KB (permuted fp16x2)
    __shared__ __align__(16) uint32_t sv[(KT / 16) * V_CHSTR]; // 8.25 KB
    __shared__ float sbias[KT];

    const int qbase = qtile * QT + warp * 32;

    // Q fragments: one LDG.128 per row thanks to gmem permutation.
    uint4 qlo[2], qhi[2];
    #pragma unroll
    for (int t = 0; t < 2; t++) {
        const uint32_t* qr = g_q + ((size_t)(h * S) + qbase + t * 16 + gid) * 16;
        qlo[t] = *(const uint4*)(qr + 4 * tig);
        qhi[t] = *(const uint4*)(qr + 8 * 16 + 4 * tig);
    }

    float o[2][5][4];   // [tile][nc 0-3 = output, 4 = ones-column row-sums]
    #pragma unroll
    for (int t = 0; t < 2; t++)
        #pragma unroll
        for (int nc = 0; nc < 5; nc++)
            #pragma unroll
            for (int r = 0; r < 4; r++) o[t][nc][r] = 0.0f;

    const uint32_t bones = (gid == 0) ? 0x3C003C00u : 0u;   // fp16 {1,1} in col 0
    const int kbase = kc * KEYS_PER_SPLIT;
    const float2* sb2 = (const float2*)sbias;

    // V fill mapping: sv address(kp, d) = chunk*V_CHSTR + 8*d + 2*(kp&3) + (kp>>2)
    const int vkey2 = tid & 63;          // key-pair id within tile (kp global)
    const int vdb   = tid >> 6;          // d-block 0..3 (8 d values each)
    const int vch   = vkey2 >> 3;        // chunk (8 key-pairs = 16 keys)
    const int vkc2  = vkey2 & 7;         // key-pair within chunk
    const int vwoff = vch * V_CHSTR + 64 * vdb + 2 * (vkc2 & 3) + (vkc2 >> 2);

    for (int jt = 0; jt < KEYS_PER_SPLIT / KT; jt++) {   // 8 tiles
        __syncthreads();
        {
            // K tile: straight copy (gmem already permuted)
            const uint4* kg4 = (const uint4*)(g_k + ((size_t)(h * S) + kbase + jt * KT) * 16);
            ((uint4*)sk)[tid]       = kg4[tid];
            ((uint4*)sk)[tid + 256] = kg4[tid + 256];

            // V tile: key-pair transpose via prmt (conflict-free STS, d-stride 8)
            const uint4* vg4 = (const uint4*)(g_v + ((size_t)(h * S) + kbase + jt * KT) * 16);
            uint4 e4 = vg4[(2 * vkey2) * 4 + vdb];       // even key, d-pairs 4vdb..+3
            uint4 o4 = vg4[(2 * vkey2) * 4 + 4 + vdb];   // odd key
            uint32_t* dst = &sv[vwoff];
            dst[0]  = __byte_perm(e4.x, o4.x, 0x5410);   // d = 8vdb+0
            dst[8]  = __byte_perm(e4.x, o4.x, 0x7632);   // d = 8vdb+1
            dst[16] = __byte_perm(e4.y, o4.y, 0x5410);   // d = 8vdb+2
            dst[24] = __byte_perm(e4.y, o4.y, 0x7632);   // d = 8vdb+3
            dst[32] = __byte_perm(e4.z, o4.z, 0x5410);   // d = 8vdb+4
            dst[40] = __byte_perm(e4.z, o4.z, 0x7632);   // d = 8vdb+5
            dst[48] = __byte_perm(e4.w, o4.w, 0x5410);   // d = 8vdb+6
            dst[56] = __byte_perm(e4.w, o4.w, 0x7632);   // d = 8vdb+7

            if (tid < KT) sbias[tid] = g_bias[kbase + jt * KT + tid];
        }
        __syncthreads();

        #pragma unroll 1
        for (int kg = 0; kg < KT / 16; kg++) {     // 8 chunks of 16 keys
            // ---- K B-frags: one LDS.128 per 8-key group ----
            const uint4 kb0 = *(const uint4*)&sk[(kg * 16 + gid) * 16 + 4 * tig];
            const uint4 kb1 = *(const uint4*)&sk[(kg * 16 + 8 + gid) * 16 + 4 * tig];

            // ---- QK^T (fp32 accum) ----
            float c[2][2][4];
            #pragma unroll
            for (int t = 0; t < 2; t++) {
                #pragma unroll
                for (int g = 0; g < 2; g++)
                    c[t][g][0] = c[t][g][1] = c[t][g][2] = c[t][g][3] = 0.0f;
                mma16(c[t][0], qlo[t].x, qhi[t].x, qlo[t].y, qhi[t].y, kb0.x, kb0.y);
                mma16(c[t][0], qlo[t].z, qhi[t].z, qlo[t].w, qhi[t].w, kb0.z, kb0.w);
                mma16(c[t][1], qlo[t].x, qhi[t].x, qlo[t].y, qhi[t].y, kb1.x, kb1.y);
                mma16(c[t][1], qlo[t].z, qhi[t].z, qlo[t].w, qhi[t].w, kb1.z, kb1.w);
            }

            float2 bg0 = sb2[kg * 8 + tig];
            float2 bg1 = sb2[kg * 8 + 4 + tig];

            // ---- softmax numerators; C-frag -> A-frag is a plain f16x2 pack ----
            uint32_t pa[2][4];
            #pragma unroll
            for (int t = 0; t < 2; t++) {
                pa[t][0] = pack_h2(ex2(c[t][0][0] + bg0.x), ex2(c[t][0][1] + bg0.y));
                pa[t][1] = pack_h2(ex2(c[t][0][2] + bg0.x), ex2(c[t][0][3] + bg0.y));
                pa[t][2] = pack_h2(ex2(c[t][1][0] + bg1.x), ex2(c[t][1][1] + bg1.y));
                pa[t][3] = pack_h2(ex2(c[t][1][2] + bg1.x), ex2(c[t][1][3] + bg1.y));
            }

            // ---- PV + ones-column row-sums ----
            const uint32_t* vb = &sv[kg * V_CHSTR + 8 * gid + 2 * tig];
            #pragma unroll
            for (int nc = 0; nc < 4; nc++) {
                uint2 vv = *(const uint2*)(vb + 64 * nc);   // d-col = 8nc + gid
                mma16(o[0][nc], pa[0][0], pa[0][1], pa[0][2], pa[0][3], vv.x, vv.y);
                mma16(o[1][nc], pa[1][0], pa[1][1], pa[1][2], pa[1][3], vv.x, vv.y);
            }
            mma16(o[0][4], pa[0][0], pa[0][1], pa[0][2], pa[0][3], bones, bones);
            mma16(o[1][4], pa[1][0], pa[1][1], pa[1][2], pa[1][3], bones, bones);
        }
    }

    // ---- write partials: l comes from the ones-column (col 0 => tig==0) ----
    #pragma unroll
    for (int t = 0; t < 2; t++) {
        const int q0 = qbase + t * 16 + gid;
        const int q1 = q0 + 8;
        const int prow0 = ((h * S) + q0) * KSPLIT + kc;
        const int prow1 = ((h * S) + q1) * KSPLIT + kc;
        if (tig == 0) {
            g_pl[prow0] = o[t][4][0];
            g_pl[prow1] = o[t][4][2];
        }
        float2* po0 = (float2*)(g_po + (size_t)prow0 * D);
        float2* po1 = (float2*)(g_po + (size_t)prow1 * D);
        #pragma unroll
        for (int nc = 0; nc < 4; nc++) {
            po0[nc * 4 + tig] = make_float2(o[t][nc][0], o[t][nc][1]);
            po1[nc * 4 + tig] = make_float2(o[t][nc][2], o[t][nc][3]);
        }
    }
}

// ---------------- kernel 3: combine split-K + sum-pool over j ---------------
__global__ __launch_bounds__(128) void reduce_kernel(float* __restrict__ out) {
    const int i = blockIdx.x;
    const int h = blockIdx.y;
    const int tid = threadIdx.x;
    const int jg = tid >> 5;
    const int d  = tid & 31;

    __shared__ float sinvL[64];
    __shared__ float sacc[128];

    if (tid < 64) {
        int s = i * 64 + tid;
        int base = (h * S + s) * KSPLIT;
        float L = 0.0f;
        #pragma unroll
        for (int k = 0; k < KSPLIT; k++) L += g_pl[base + k];
        sinvL[tid] = 1.0f / L;
    }
    __syncthreads();

    float acc = 0.0f;
    #pragma unroll 4
    for (int jj = 0; jj < 16; jj++) {
        int j = jg * 16 + jj;
        int s = i * 64 + j;
        size_t base = ((size_t)(h * S + s) * KSPLIT) * D + d;
        float ov = 0.0f;
        #pragma unroll
        for (int k = 0; k < KSPLIT; k++) ov += g_po[base + (size_t)k * D];
        acc += ov * sinvL[j];
    }

    sacc[tid] = acc;
    __syncthreads();
    if (tid < 32) {
        float r = sacc[tid] + sacc[tid + 32] + sacc[tid + 64] + sacc[tid + 96];
        out[i * HD + h * 32 + tid] = r;
    }
}

// ---------------- launch ----------------------------------------------------
extern "C" void kernel_launch(void* const* d_in, const int* in_sizes, int n_in,
                              void* d_out, int out_size) {
    const float* x    = (const float*)d_in[0];
    const int*   mask = (const int*)  d_in[1];
    const float* Wq   = (const float*)d_in[2];
    const float* bq   = (const float*)d_in[3];
    const float* Wk   = (const float*)d_in[4];
    const float* bk   = (const float*)d_in[5];
    const float* Wv   = (const float*)d_in[6];
    const float* bv   = (const float*)d_in[7];
    float* out = (float*)d_out;

    bias_kernel<<<4, 1024>>>(mask);
    proj_kernel<<<dim3(S / 32, 3), 256>>>(x, Wq, bq, Wk, bk, Wv, bv);
    attn_kernel<<<dim3(S / QT, H, KSPLIT), 256>>>();
    reduce_kernel<<<dim3(64, H), 128>>>(out);
}